// round 6
// baseline (speedup 1.0000x reference)
#include <cuda_runtime.h>
#include <cuda_bf16.h>
#include <stdint.h>

// LSTM_558345748830 v5 (resubmit after infra failure): anti-phased dual-group
// tensor-core recurrence. 256 threads = 2 groups x 4 warps; group A (warps 0-3)
// and group B (warps 4-7) each run 16 batches, scheduled half a step apart so
// every SMSP always has one warp in the MUFU-heavy elementwise phase and one in
// the mma-heavy GEMM phase.

#define Tn 512
#define Hn 32
#define NB 16        // batches per group
#define NT 256
#define Bn 4096
#define GPAD 132

__device__ __forceinline__ float tanhap(float x) {
    float y;
    asm("tanh.approx.f32 %0, %1;" : "=f"(y) : "f"(x));
    return y;
}
__device__ __forceinline__ float sigap(float x) {
    return fmaf(tanhap(0.5f * x), 0.5f, 0.5f);
}
__device__ __forceinline__ void mma_bf16(float* d, const uint32_t* a, const uint32_t* b) {
    asm volatile(
        "mma.sync.aligned.m16n8k16.row.col.f32.bf16.bf16.f32 "
        "{%0,%1,%2,%3}, {%4,%5,%6,%7}, {%8,%9}, {%0,%1,%2,%3};"
        : "+f"(d[0]), "+f"(d[1]), "+f"(d[2]), "+f"(d[3])
        : "r"(a[0]), "r"(a[1]), "r"(a[2]), "r"(a[3]), "r"(b[0]), "r"(b[1]));
}
__device__ __forceinline__ uint32_t pack2(float e_even, float e_odd) {
    uint32_t r;
    asm("cvt.rn.bf16x2.f32 %0, %1, %2;" : "=r"(r) : "f"(e_odd), "f"(e_even));
    return r;
}
__device__ __forceinline__ float bf16rt(float v) {
    return __bfloat162float(__float2bfloat16_rn(v));
}
__device__ __forceinline__ void split_store(uint16_t* H, uint16_t* L, int idx, float v) {
    __nv_bfloat16 bh = __float2bfloat16_rn(v);
    float fh = __bfloat162float(bh);
    __nv_bfloat16 bl = __float2bfloat16_rn(v - fh);
    H[idx] = *reinterpret_cast<uint16_t*>(&bh);
    L[idx] = *reinterpret_cast<uint16_t*>(&bl);
}

__global__ __launch_bounds__(NT, 1)
void lstm_tc3(const float* __restrict__ x,
              const float* __restrict__ w_ih_0, const float* __restrict__ w_hh_0,
              const float* __restrict__ b_ih_0, const float* __restrict__ b_hh_0,
              const float* __restrict__ w_ih_1, const float* __restrict__ w_hh_1,
              const float* __restrict__ b_ih_1, const float* __restrict__ b_hh_1,
              const float* __restrict__ fc_w,   const float* __restrict__ fc_b,
              float* __restrict__ out)
{
    __shared__ float    gts1[2][NB][GPAD];   // per-group gate staging, layer 1
    __shared__ float    gts2[2][NB][GPAD];   // per-group gate staging, layer 2
    __shared__ uint32_t fragH[2][512];       // per-group A-frags hi (kt0-1 h1, kt2-3 h2)
    __shared__ uint32_t fragL[2][512];       // per-group A-frags lo

    const int tid   = threadIdx.x;
    const int lane  = tid & 31;
    const int warp  = tid >> 5;
    const int grp   = warp >> 2;       // 0 = group A, 1 = group B
    const int gw    = warp & 3;        // warp within group
    const int g     = lane >> 2;
    const int t4    = lane & 3;
    const int wbase = gw * 32;         // 32 gate columns per warp
    const int bb    = blockIdx.x * (2 * NB) + grp * NB;
    const float* xg = x + (size_t)bb * Tn;

    for (int i = tid; i < 2 * 512; i += NT) {
        (&fragH[0][0])[i] = 0u;
        (&fragL[0][0])[i] = 0u;
    }

    // ---- weight B-fragments (hi/lo split), 4 ntiles per warp ----
    uint32_t B1h[4][2][2], B1l[4][2][2];
    uint32_t B2h[4][4][2], B2l[4][4][2];
    #pragma unroll
    for (int nt = 0; nt < 4; nt++) {
        const int n = wbase + nt * 8 + g;
        const float* w0 = w_hh_0 + n * Hn;
        #pragma unroll
        for (int kt = 0; kt < 2; kt++) {
            #pragma unroll
            for (int h = 0; h < 2; h++) {
                int k = kt * 16 + 2 * t4 + 8 * h;
                float we = w0[k], wo = w0[k + 1];
                float he = bf16rt(we), ho = bf16rt(wo);
                B1h[nt][kt][h] = pack2(he, ho);
                B1l[nt][kt][h] = pack2(we - he, wo - ho);
            }
        }
        const float* wi1 = w_ih_1 + n * Hn;
        const float* wh1 = w_hh_1 + n * Hn;
        #pragma unroll
        for (int kt = 0; kt < 4; kt++) {
            const float* ws = (kt < 2) ? (wi1 + kt * 16) : (wh1 + (kt - 2) * 16);
            #pragma unroll
            for (int h = 0; h < 2; h++) {
                int k = 2 * t4 + 8 * h;
                float we = ws[k], wo = ws[k + 1];
                float he = bf16rt(we), ho = bf16rt(wo);
                B2h[nt][kt][h] = pack2(he, ho);
                B2l[nt][kt][h] = pack2(we - he, wo - ho);
            }
        }
    }

    // ---- epilogue constants (8 gate columns per thread) ----
    float wx[8], bi0[8], bi1[8];
    #pragma unroll
    for (int q = 0; q < 8; q++) {
        int n = wbase + (q >> 1) * 8 + 2 * t4 + (q & 1);
        wx[q]  = w_ih_0[n];
        bi0[q] = b_ih_0[n] + b_hh_0[n];
        bi1[q] = b_ih_1[n] + b_hh_1[n];
    }

    // ---- elementwise fragment indices: 4 (b,j) pairs, b = gw + 4*pp, j = lane ----
    int fi1[4], fi2[4];
    {
        const int kc  = lane & 15;
        const int ktl = lane >> 4;
        const int rlo = (kc >= 8) ? 2 : 0;
        #pragma unroll
        for (int pp = 0; pp < 4; pp++) {
            int b   = gw + 4 * pp;
            int reg = rlo + ((b >= 8) ? 1 : 0);
            int ln  = (b & 7) * 4 + ((kc & 7) >> 1);
            fi1[pp] = ((ktl * 4 + reg) * 32 + ln) * 2 + (kc & 1);
            fi2[pp] = (((ktl + 2) * 4 + reg) * 32 + ln) * 2 + (kc & 1);
        }
    }
    float c1[4] = {0.f, 0.f, 0.f, 0.f}, c2[4] = {0.f, 0.f, 0.f, 0.f};
    const float fw = fc_w[lane];

    uint16_t* FH = (uint16_t*)&fragH[grp][0];
    uint16_t* FL = (uint16_t*)&fragL[grp][0];

    // ---- Phase E: elementwise for own group's 16 batches -> write A-frags ----
    auto phaseE = [&](bool skip2) {
        #pragma unroll
        for (int pp = 0; pp < 4; pp++) {
            const int b = gw + 4 * pp;
            float gi = gts1[grp][b][lane],          gf = gts1[grp][b][Hn + lane];
            float gg = gts1[grp][b][2 * Hn + lane], go = gts1[grp][b][3 * Hn + lane];
            float i_ = sigap(gi), f_ = sigap(gf), g_ = tanhap(gg), o_ = sigap(go);
            c1[pp] = fmaf(f_, c1[pp], i_ * g_);
            split_store(FH, FL, fi1[pp], o_ * tanhap(c1[pp]));
            if (!skip2) {
                gi = gts2[grp][b][lane];          gf = gts2[grp][b][Hn + lane];
                gg = gts2[grp][b][2 * Hn + lane]; go = gts2[grp][b][3 * Hn + lane];
                i_ = sigap(gi); f_ = sigap(gf); g_ = tanhap(gg); o_ = sigap(go);
                c2[pp] = fmaf(f_, c2[pp], i_ * g_);
                split_store(FH, FL, fi2[pp], o_ * tanhap(c2[pp]));
            }
        }
    };

    // ---- Phase M: gates1(t+1) and gates2(t) for own group ----
    auto phaseM = [&](int tt) {
        uint32_t Ah[4][4], Al[4][4];
        #pragma unroll
        for (int kt = 0; kt < 4; kt++) {
            #pragma unroll
            for (int r = 0; r < 4; r++) {
                Ah[kt][r] = fragH[grp][(kt * 4 + r) * 32 + lane];
                Al[kt][r] = fragL[grp][(kt * 4 + r) * 32 + lane];
            }
        }
        if (tt < Tn - 1) {
            const float xv0 = __ldg(&xg[g * Tn + tt + 1]);
            const float xv1 = __ldg(&xg[(g + 8) * Tn + tt + 1]);
            #pragma unroll
            for (int nt = 0; nt < 4; nt++) {
                float acc[4] = {0.f, 0.f, 0.f, 0.f};
                #pragma unroll
                for (int kt = 0; kt < 2; kt++) {
                    mma_bf16(acc, Ah[kt], B1h[nt][kt]);
                    mma_bf16(acc, Al[kt], B1h[nt][kt]);
                    mma_bf16(acc, Ah[kt], B1l[nt][kt]);
                }
                acc[0] += fmaf(wx[nt * 2 + 0], xv0, bi0[nt * 2 + 0]);
                acc[1] += fmaf(wx[nt * 2 + 1], xv0, bi0[nt * 2 + 1]);
                acc[2] += fmaf(wx[nt * 2 + 0], xv1, bi0[nt * 2 + 0]);
                acc[3] += fmaf(wx[nt * 2 + 1], xv1, bi0[nt * 2 + 1]);
                const int n0 = wbase + nt * 8 + 2 * t4;
                *(float2*)&gts1[grp][g][n0]     = make_float2(acc[0], acc[1]);
                *(float2*)&gts1[grp][g + 8][n0] = make_float2(acc[2], acc[3]);
            }
        }
        #pragma unroll
        for (int nt = 0; nt < 4; nt++) {
            float acc[4] = {0.f, 0.f, 0.f, 0.f};
            #pragma unroll
            for (int kt = 0; kt < 4; kt++) {
                mma_bf16(acc, Ah[kt], B2h[nt][kt]);
                mma_bf16(acc, Al[kt], B2h[nt][kt]);
                mma_bf16(acc, Ah[kt], B2l[nt][kt]);
            }
            acc[0] += bi1[nt * 2 + 0];
            acc[1] += bi1[nt * 2 + 1];
            acc[2] += bi1[nt * 2 + 0];
            acc[3] += bi1[nt * 2 + 1];
            const int n0 = wbase + nt * 8 + 2 * t4;
            *(float2*)&gts2[grp][g][n0]     = make_float2(acc[0], acc[1]);
            *(float2*)&gts2[grp][g + 8][n0] = make_float2(acc[2], acc[3]);
        }
    };

    // ---- prologue: gates1(0) for own group ----
    {
        const float xv0 = __ldg(&xg[g * Tn]);
        const float xv1 = __ldg(&xg[(g + 8) * Tn]);
        #pragma unroll
        for (int nt = 0; nt < 4; nt++) {
            const int n0 = wbase + nt * 8 + 2 * t4;
            gts1[grp][g][n0 + 0]     = fmaf(wx[nt * 2 + 0], xv0, bi0[nt * 2 + 0]);
            gts1[grp][g][n0 + 1]     = fmaf(wx[nt * 2 + 1], xv0, bi0[nt * 2 + 1]);
            gts1[grp][g + 8][n0 + 0] = fmaf(wx[nt * 2 + 0], xv1, bi0[nt * 2 + 0]);
            gts1[grp][g + 8][n0 + 1] = fmaf(wx[nt * 2 + 1], xv1, bi0[nt * 2 + 1]);
        }
    }
    __syncthreads();
    if (grp == 1) phaseE(true);   // group B runs E(0) up front -> half-step lead
    __syncthreads();

    // ---- main loop: A and B permanently anti-phased ----
    for (int t = 0; t < Tn; t++) {
        if (grp == 0) phaseE(t == 0);      // A: elementwise(t)   B: mma(t)
        else          phaseM(t);
        __syncthreads();
        if (grp == 0) phaseM(t);           // A: mma(t)           B: elementwise(t+1)
        else if (t < Tn - 1) phaseE(false);
        __syncthreads();
    }

    // ---- epilogue: h2(Tn-1) from gates2(Tn-1), FC via shuffle reduce ----
    #pragma unroll
    for (int pp = 0; pp < 4; pp++) {
        const int b = gw + 4 * pp;
        float gi = gts2[grp][b][lane],          gf = gts2[grp][b][Hn + lane];
        float gg = gts2[grp][b][2 * Hn + lane], go = gts2[grp][b][3 * Hn + lane];
        float i_ = sigap(gi), f_ = sigap(gf), g_ = tanhap(gg), o_ = sigap(go);
        c2[pp] = fmaf(f_, c2[pp], i_ * g_);
        float prod = (o_ * tanhap(c2[pp])) * fw;
        #pragma unroll
        for (int off = 16; off >= 1; off >>= 1)
            prod += __shfl_xor_sync(0xffffffffu, prod, off);
        if (lane == 0) out[bb + b] = prod + fc_b[0];
    }
}

extern "C" void kernel_launch(void* const* d_in, const int* in_sizes, int n_in,
                              void* d_out, int out_size)
{
    (void)in_sizes; (void)n_in; (void)out_size;
    const float* x      = (const float*)d_in[0];
    const float* w_ih_0 = (const float*)d_in[1];
    const float* w_hh_0 = (const float*)d_in[2];
    const float* b_ih_0 = (const float*)d_in[3];
    const float* b_hh_0 = (const float*)d_in[4];
    const float* w_ih_1 = (const float*)d_in[5];
    const float* w_hh_1 = (const float*)d_in[6];
    const float* b_ih_1 = (const float*)d_in[7];
    const float* b_hh_1 = (const float*)d_in[8];
    const float* fc_w   = (const float*)d_in[9];
    const float* fc_b   = (const float*)d_in[10];
    float* o = (float*)d_out;

    dim3 grid(Bn / (2 * NB));   // 128 blocks, 1 per SM
    dim3 block(NT);             // 256 threads = 2 anti-phased groups
    lstm_tc3<<<grid, block>>>(x, w_ih_0, w_hh_0, b_ih_0, b_hh_0,
                              w_ih_1, w_hh_1, b_ih_1, b_hh_1,
                              fc_w, fc_b, o);
}

// round 7
// speedup vs baseline: 1.5822x; 1.5822x over previous
#include <cuda_runtime.h>
#include <cuda_bf16.h>
#include <stdint.h>

// LSTM_558345748830 v6: register-resident gates.
// Block = 128 threads = 4 warps = one 16-batch group. Warp w owns gate ntiles
// {w, w+4, w+8, w+12} (stride 4) so ntile == gate index and each thread's mma
// accumulators hold all 4 gates (i,f,g,o) for its (batch,hidden) pairs.
// Elementwise runs on registers; only h is exchanged via smem A-frag slabs
// (double-buffered). ONE __syncthreads per timestep.

#define Tn 512
#define Hn 32
#define NB 16
#define NT 128
#define Bn 4096

__device__ __forceinline__ float tanhap(float x) {
    float y;
    asm("tanh.approx.f32 %0, %1;" : "=f"(y) : "f"(x));
    return y;
}
__device__ __forceinline__ float sigap(float x) {
    return fmaf(tanhap(0.5f * x), 0.5f, 0.5f);
}
__device__ __forceinline__ void mma_bf16(float* d, const uint32_t* a, const uint32_t* b) {
    asm volatile(
        "mma.sync.aligned.m16n8k16.row.col.f32.bf16.bf16.f32 "
        "{%0,%1,%2,%3}, {%4,%5,%6,%7}, {%8,%9}, {%0,%1,%2,%3};"
        : "+f"(d[0]), "+f"(d[1]), "+f"(d[2]), "+f"(d[3])
        : "r"(a[0]), "r"(a[1]), "r"(a[2]), "r"(a[3]), "r"(b[0]), "r"(b[1]));
}
__device__ __forceinline__ uint32_t pack2(float e_even, float e_odd) {
    uint32_t r;
    asm("cvt.rn.bf16x2.f32 %0, %1, %2;" : "=r"(r) : "f"(e_odd), "f"(e_even));
    return r;
}
__device__ __forceinline__ float bf16rt(float v) {
    return __bfloat162float(__float2bfloat16_rn(v));
}

__global__ __launch_bounds__(NT, 2)
void lstm_tc4(const float* __restrict__ x,
              const float* __restrict__ w_ih_0, const float* __restrict__ w_hh_0,
              const float* __restrict__ b_ih_0, const float* __restrict__ b_hh_0,
              const float* __restrict__ w_ih_1, const float* __restrict__ w_hh_1,
              const float* __restrict__ b_ih_1, const float* __restrict__ b_hh_1,
              const float* __restrict__ fc_w,   const float* __restrict__ fc_b,
              float* __restrict__ out)
{
    __shared__ uint32_t fragH[2][512];   // [buf][(kt*4+r)*32+lane]; kt0-1=h1, kt2-3=h2
    __shared__ uint32_t fragL[2][512];
    __shared__ float    hf[NB][Hn + 1];  // final h2 for FC head

    const int tid  = threadIdx.x;
    const int lane = tid & 31;
    const int w    = tid >> 5;        // warp 0..3
    const int g    = lane >> 2;       // mma group row 0..7
    const int t4   = lane & 3;
    const int b0   = blockIdx.x * NB;
    const float* xg = x + (size_t)b0 * Tn;

    // zero both frag buffers (h1(-1)=h2(-1)=0)
    for (int i = tid; i < 2 * 512; i += NT) {
        (&fragH[0][0])[i] = 0u;
        (&fragL[0][0])[i] = 0u;
    }

    // ---- weight B-fragments; ntile(nt) = w + 4*nt  (nt == gate index) ----
    uint32_t B1h[4][2][2], B1l[4][2][2];    // layer1 W_hh_0 [gate][ktile][half]
    uint32_t B2h[4][4][2], B2l[4][4][2];    // layer2 [W_ih_1 | W_hh_1]
    #pragma unroll
    for (int nt = 0; nt < 4; nt++) {
        const int n = (w + 4 * nt) * 8 + g;       // global gate row
        const float* w0 = w_hh_0 + n * Hn;
        #pragma unroll
        for (int kt = 0; kt < 2; kt++) {
            #pragma unroll
            for (int h = 0; h < 2; h++) {
                int k = kt * 16 + 2 * t4 + 8 * h;
                float we = w0[k], wo = w0[k + 1];
                float he = bf16rt(we), ho = bf16rt(wo);
                B1h[nt][kt][h] = pack2(he, ho);
                B1l[nt][kt][h] = pack2(we - he, wo - ho);
            }
        }
        const float* wi1 = w_ih_1 + n * Hn;
        const float* wh1 = w_hh_1 + n * Hn;
        #pragma unroll
        for (int kt = 0; kt < 4; kt++) {
            const float* ws = (kt < 2) ? (wi1 + kt * 16) : (wh1 + (kt - 2) * 16);
            #pragma unroll
            for (int h = 0; h < 2; h++) {
                int k = 2 * t4 + 8 * h;
                float we = ws[k], wo = ws[k + 1];
                float he = bf16rt(we), ho = bf16rt(wo);
                B2h[nt][kt][h] = pack2(he, ho);
                B2l[nt][kt][h] = pack2(we - he, wo - ho);
            }
        }
    }

    // ---- epilogue constants per (gate nt, parity) ----
    float wx[8], bi0[8], bi1[8];
    #pragma unroll
    for (int q = 0; q < 8; q++) {
        int n = (w + 4 * (q >> 1)) * 8 + 2 * t4 + (q & 1);
        wx[q]  = w_ih_0[n];
        bi0[q] = b_ih_0[n] + b_hh_0[n];
        bi1[q] = b_ih_1[n] + b_hh_1[n];
    }

    // frag store slots for this thread's h values (j = 8w + 2t4, rows g / g+8)
    const int sl1 = (((w >> 1) * 4) + (w & 1) * 2) * 32 + lane;  // layer1, row g (r even)
    // row g+8 at sl1+32 (r+1); layer2 (kt+2) at sl1+256.

    // accumulators / cell state
    float g1acc[4][4], g2acc[4][4];   // [gate][p]; p0=(g,even) p1=(g,odd) p2=(g+8,even) p3=(g+8,odd)
    float c1[4] = {0.f, 0.f, 0.f, 0.f};
    float c2[4] = {0.f, 0.f, 0.f, 0.f};

    // ---- prologue: g1acc = gates1(0) = wx*x(0) + b0 ----
    {
        const float xv0 = __ldg(&xg[g * Tn]);
        const float xv1 = __ldg(&xg[(g + 8) * Tn]);
        #pragma unroll
        for (int nt = 0; nt < 4; nt++) {
            g1acc[nt][0] = fmaf(wx[nt * 2 + 0], xv0, bi0[nt * 2 + 0]);
            g1acc[nt][1] = fmaf(wx[nt * 2 + 1], xv0, bi0[nt * 2 + 1]);
            g1acc[nt][2] = fmaf(wx[nt * 2 + 0], xv1, bi0[nt * 2 + 0]);
            g1acc[nt][3] = fmaf(wx[nt * 2 + 1], xv1, bi0[nt * 2 + 1]);
        }
    }
    __syncthreads();

    for (int t = 0; t < Tn; t++) {
        const int buf = t & 1;
        // ======== Phase E (registers): h1(t) from g1acc, h2(t-1) from g2acc ========
        {
            float h1v[4];
            #pragma unroll
            for (int p = 0; p < 4; p++) {
                float i_ = sigap(g1acc[0][p]);
                float f_ = sigap(g1acc[1][p]);
                float g_ = tanhap(g1acc[2][p]);
                float o_ = sigap(g1acc[3][p]);
                c1[p] = fmaf(f_, c1[p], i_ * g_);
                h1v[p] = o_ * tanhap(c1[p]);
            }
            // pack + store layer-1 A-frags: rows g (p0,p1) and g+8 (p2,p3)
            float e0 = bf16rt(h1v[0]), o0 = bf16rt(h1v[1]);
            float e1 = bf16rt(h1v[2]), o1 = bf16rt(h1v[3]);
            fragH[buf][sl1]      = pack2(e0, o0);
            fragH[buf][sl1 + 32] = pack2(e1, o1);
            fragL[buf][sl1]      = pack2(h1v[0] - e0, h1v[1] - o0);
            fragL[buf][sl1 + 32] = pack2(h1v[2] - e1, h1v[3] - o1);

            if (t > 0) {
                float h2v[4];
                #pragma unroll
                for (int p = 0; p < 4; p++) {
                    float i_ = sigap(g2acc[0][p]);
                    float f_ = sigap(g2acc[1][p]);
                    float g_ = tanhap(g2acc[2][p]);
                    float o_ = sigap(g2acc[3][p]);
                    c2[p] = fmaf(f_, c2[p], i_ * g_);
                    h2v[p] = o_ * tanhap(c2[p]);
                }
                float f0 = bf16rt(h2v[0]), q0 = bf16rt(h2v[1]);
                float f1 = bf16rt(h2v[2]), q1 = bf16rt(h2v[3]);
                fragH[buf][sl1 + 256]      = pack2(f0, q0);
                fragH[buf][sl1 + 288]      = pack2(f1, q1);
                fragL[buf][sl1 + 256]      = pack2(h2v[0] - f0, h2v[1] - q0);
                fragL[buf][sl1 + 288]      = pack2(h2v[2] - f1, h2v[3] - q1);
            }
        }
        __syncthreads();   // the ONLY barrier per step

        // ======== Phase M: g1acc <- gates1(t+1);  g2acc <- gates2(t) ========
        uint32_t Ah[4][4], Al[4][4];
        #pragma unroll
        for (int kt = 0; kt < 4; kt++) {
            #pragma unroll
            for (int r = 0; r < 4; r++) {
                Ah[kt][r] = fragH[buf][(kt * 4 + r) * 32 + lane];
                Al[kt][r] = fragL[buf][(kt * 4 + r) * 32 + lane];
            }
        }
        if (t < Tn - 1) {
            const float xv0 = __ldg(&xg[g * Tn + t + 1]);
            const float xv1 = __ldg(&xg[(g + 8) * Tn + t + 1]);
            #pragma unroll
            for (int nt = 0; nt < 4; nt++) {
                g1acc[nt][0] = fmaf(wx[nt * 2 + 0], xv0, bi0[nt * 2 + 0]);
                g1acc[nt][1] = fmaf(wx[nt * 2 + 1], xv0, bi0[nt * 2 + 1]);
                g1acc[nt][2] = fmaf(wx[nt * 2 + 0], xv1, bi0[nt * 2 + 0]);
                g1acc[nt][3] = fmaf(wx[nt * 2 + 1], xv1, bi0[nt * 2 + 1]);
                #pragma unroll
                for (int kt = 0; kt < 2; kt++) {
                    mma_bf16(g1acc[nt], Ah[kt], B1h[nt][kt]);
                    mma_bf16(g1acc[nt], Al[kt], B1h[nt][kt]);
                    mma_bf16(g1acc[nt], Ah[kt], B1l[nt][kt]);
                }
            }
        }
        #pragma unroll
        for (int nt = 0; nt < 4; nt++) {
            g2acc[nt][0] = bi1[nt * 2 + 0];
            g2acc[nt][1] = bi1[nt * 2 + 1];
            g2acc[nt][2] = bi1[nt * 2 + 0];
            g2acc[nt][3] = bi1[nt * 2 + 1];
            #pragma unroll
            for (int kt = 0; kt < 4; kt++) {
                mma_bf16(g2acc[nt], Ah[kt], B2h[nt][kt]);
                mma_bf16(g2acc[nt], Al[kt], B2h[nt][kt]);
                mma_bf16(g2acc[nt], Ah[kt], B2l[nt][kt]);
            }
        }
        // no second barrier: E(t+1) writes buf^1 while stragglers read buf
    }

    // ---- epilogue: h2(Tn-1) from g2acc(Tn-1), FC head ----
    {
        const int j = 8 * w + 2 * t4;
        #pragma unroll
        for (int p = 0; p < 4; p++) {
            float i_ = sigap(g2acc[0][p]);
            float f_ = sigap(g2acc[1][p]);
            float g_ = tanhap(g2acc[2][p]);
            float o_ = sigap(g2acc[3][p]);
            c2[p] = fmaf(f_, c2[p], i_ * g_);
            float hv = o_ * tanhap(c2[p]);
            hf[(p < 2) ? g : (g + 8)][j + (p & 1)] = hv;
        }
    }
    __syncthreads();
    if (tid < NB) {
        float a = fc_b[0];
        #pragma unroll
        for (int k = 0; k < Hn; k++) a = fmaf(hf[tid][k], fc_w[k], a);
        out[b0 + tid] = a;
    }
}

extern "C" void kernel_launch(void* const* d_in, const int* in_sizes, int n_in,
                              void* d_out, int out_size)
{
    (void)in_sizes; (void)n_in; (void)out_size;
    const float* x      = (const float*)d_in[0];
    const float* w_ih_0 = (const float*)d_in[1];
    const float* w_hh_0 = (const float*)d_in[2];
    const float* b_ih_0 = (const float*)d_in[3];
    const float* b_hh_0 = (const float*)d_in[4];
    const float* w_ih_1 = (const float*)d_in[5];
    const float* w_hh_1 = (const float*)d_in[6];
    const float* b_ih_1 = (const float*)d_in[7];
    const float* b_hh_1 = (const float*)d_in[8];
    const float* fc_w   = (const float*)d_in[9];
    const float* fc_b   = (const float*)d_in[10];
    float* o = (float*)d_out;

    dim3 grid(Bn / NB);   // 256 blocks x 128 thr -> 2 blocks/SM, single wave
    dim3 block(NT);
    lstm_tc4<<<grid, block>>>(x, w_ih_0, w_hh_0, b_ih_0, b_hh_0,
                              w_ih_1, w_hh_1, b_ih_1, b_hh_1,
                              fc_w, fc_b, o);
}

// round 8
// speedup vs baseline: 1.6189x; 1.0232x over previous
#include <cuda_runtime.h>
#include <cuda_fp16.h>
#include <stdint.h>

// LSTM_558345748830 v7: fp16 2-pass split, register-resident gates.
// Block = 128 threads = 4 warps = one 16-batch group; warp w owns gate ntiles
// {w, w+4, w+8, w+12} so each thread's mma accumulators hold all 4 gates.
// gates = (Ah + Al) . B  with A = h split into fp16 hi + fp16 residual and
// B = weights in single fp16 (weight perturbation ~2^-11; recurrence contracts).
// Dual accumulator chains (hi-pass / lo-pass) double mma ILP. One barrier/step.

#define Tn 512
#define Hn 32
#define NB 16
#define NT 128
#define Bn 4096

__device__ __forceinline__ float tanhap(float x) {
    float y;
    asm("tanh.approx.f32 %0, %1;" : "=f"(y) : "f"(x));
    return y;
}
__device__ __forceinline__ float sigap(float x) {
    return fmaf(tanhap(0.5f * x), 0.5f, 0.5f);
}
__device__ __forceinline__ void mma_f16(float* d, const uint32_t* a, const uint32_t* b) {
    asm volatile(
        "mma.sync.aligned.m16n8k16.row.col.f32.f16.f16.f32 "
        "{%0,%1,%2,%3}, {%4,%5,%6,%7}, {%8,%9}, {%0,%1,%2,%3};"
        : "+f"(d[0]), "+f"(d[1]), "+f"(d[2]), "+f"(d[3])
        : "r"(a[0]), "r"(a[1]), "r"(a[2]), "r"(a[3]), "r"(b[0]), "r"(b[1]));
}
// pack {even-k -> low half, odd-k -> high half}
__device__ __forceinline__ uint32_t pack2(float e_even, float e_odd) {
    uint32_t r;
    asm("cvt.rn.f16x2.f32 %0, %1, %2;" : "=r"(r) : "f"(e_odd), "f"(e_even));
    return r;
}
__device__ __forceinline__ float f16rt(float v) {
    return __half2float(__float2half_rn(v));
}

__global__ __launch_bounds__(NT, 2)
void lstm_tc5(const float* __restrict__ x,
              const float* __restrict__ w_ih_0, const float* __restrict__ w_hh_0,
              const float* __restrict__ b_ih_0, const float* __restrict__ b_hh_0,
              const float* __restrict__ w_ih_1, const float* __restrict__ w_hh_1,
              const float* __restrict__ b_ih_1, const float* __restrict__ b_hh_1,
              const float* __restrict__ fc_w,   const float* __restrict__ fc_b,
              float* __restrict__ out)
{
    __shared__ uint2 frag[2][512];       // [buf][(kt*4+r)*32+lane]; .x=hi .y=lo
    __shared__ float hf[NB][Hn + 1];     // final h2 for FC head

    const int tid  = threadIdx.x;
    const int lane = tid & 31;
    const int w    = tid >> 5;        // warp 0..3
    const int g    = lane >> 2;       // mma group row 0..7
    const int t4   = lane & 3;
    const int b0   = blockIdx.x * NB;
    const float* xg = x + (size_t)b0 * Tn;

    for (int i = tid; i < 2 * 512; i += NT)
        (&frag[0][0])[i] = make_uint2(0u, 0u);

    // ---- weight B-fragments (single fp16); ntile(nt) = w + 4*nt = gate index ----
    uint32_t B1[4][2][2];    // layer1 W_hh_0 [gate][ktile][half]
    uint32_t B2[4][4][2];    // layer2 [W_ih_1 | W_hh_1]
    #pragma unroll
    for (int nt = 0; nt < 4; nt++) {
        const int n = (w + 4 * nt) * 8 + g;       // global gate row
        const float* w0 = w_hh_0 + n * Hn;
        #pragma unroll
        for (int kt = 0; kt < 2; kt++)
            #pragma unroll
            for (int h = 0; h < 2; h++) {
                int k = kt * 16 + 2 * t4 + 8 * h;
                B1[nt][kt][h] = pack2(w0[k], w0[k + 1]);
            }
        const float* wi1 = w_ih_1 + n * Hn;
        const float* wh1 = w_hh_1 + n * Hn;
        #pragma unroll
        for (int kt = 0; kt < 4; kt++) {
            const float* ws = (kt < 2) ? (wi1 + kt * 16) : (wh1 + (kt - 2) * 16);
            #pragma unroll
            for (int h = 0; h < 2; h++) {
                int k = 2 * t4 + 8 * h;
                B2[nt][kt][h] = pack2(ws[k], ws[k + 1]);
            }
        }
    }

    // ---- epilogue constants per (gate nt, parity) ----
    float wx[8], bi0[8], bi1[8];
    #pragma unroll
    for (int q = 0; q < 8; q++) {
        int n = (w + 4 * (q >> 1)) * 8 + 2 * t4 + (q & 1);
        wx[q]  = w_ih_0[n];
        bi0[q] = b_ih_0[n] + b_hh_0[n];
        bi1[q] = b_ih_1[n] + b_hh_1[n];
    }

    // frag store slot: this thread's h pair (j = 8w+2t4) row g; +32 = row g+8;
    // +256 = layer-2 region (kt+2).
    const int sl1 = (((w >> 1) * 4) + (w & 1) * 2) * 32 + lane;

    float g1acc[4][4], g2acc[4][4];   // [gate][p]
    float c1[4] = {0.f, 0.f, 0.f, 0.f};
    float c2[4] = {0.f, 0.f, 0.f, 0.f};

    // ---- prologue: g1acc = gates1(0) ----
    {
        const float xv0 = __ldg(&xg[g * Tn]);
        const float xv1 = __ldg(&xg[(g + 8) * Tn]);
        #pragma unroll
        for (int nt = 0; nt < 4; nt++) {
            g1acc[nt][0] = fmaf(wx[nt * 2 + 0], xv0, bi0[nt * 2 + 0]);
            g1acc[nt][1] = fmaf(wx[nt * 2 + 1], xv0, bi0[nt * 2 + 1]);
            g1acc[nt][2] = fmaf(wx[nt * 2 + 0], xv1, bi0[nt * 2 + 0]);
            g1acc[nt][3] = fmaf(wx[nt * 2 + 1], xv1, bi0[nt * 2 + 1]);
        }
    }
    __syncthreads();

    for (int t = 0; t < Tn; t++) {
        const int buf = t & 1;
        // ======== Phase E (registers): h1(t) from g1acc, h2(t-1) from g2acc ========
        {
            float h1v[4];
            #pragma unroll
            for (int p = 0; p < 4; p++) {
                float i_ = sigap(g1acc[0][p]);
                float f_ = sigap(g1acc[1][p]);
                float g_ = tanhap(g1acc[2][p]);
                float o_ = sigap(g1acc[3][p]);
                c1[p] = fmaf(f_, c1[p], i_ * g_);
                h1v[p] = o_ * tanhap(c1[p]);
            }
            float e0 = f16rt(h1v[0]), o0 = f16rt(h1v[1]);
            float e1 = f16rt(h1v[2]), o1 = f16rt(h1v[3]);
            frag[buf][sl1]      = make_uint2(pack2(e0, o0),
                                             pack2(h1v[0] - e0, h1v[1] - o0));
            frag[buf][sl1 + 32] = make_uint2(pack2(e1, o1),
                                             pack2(h1v[2] - e1, h1v[3] - o1));
            if (t > 0) {
                float h2v[4];
                #pragma unroll
                for (int p = 0; p < 4; p++) {
                    float i_ = sigap(g2acc[0][p]);
                    float f_ = sigap(g2acc[1][p]);
                    float g_ = tanhap(g2acc[2][p]);
                    float o_ = sigap(g2acc[3][p]);
                    c2[p] = fmaf(f_, c2[p], i_ * g_);
                    h2v[p] = o_ * tanhap(c2[p]);
                }
                float f0 = f16rt(h2v[0]), q0 = f16rt(h2v[1]);
                float f1 = f16rt(h2v[2]), q1 = f16rt(h2v[3]);
                frag[buf][sl1 + 256] = make_uint2(pack2(f0, q0),
                                                  pack2(h2v[0] - f0, h2v[1] - q0));
                frag[buf][sl1 + 288] = make_uint2(pack2(f1, q1),
                                                  pack2(h2v[2] - f1, h2v[3] - q1));
            }
        }
        __syncthreads();   // the ONLY barrier per step

        // ======== Phase M: g1acc <- gates1(t+1);  g2acc <- gates2(t) ========
        uint32_t Ah[4][4], Al[4][4];
        #pragma unroll
        for (int kt = 0; kt < 4; kt++)
            #pragma unroll
            for (int r = 0; r < 4; r++) {
                uint2 v = frag[buf][(kt * 4 + r) * 32 + lane];
                Ah[kt][r] = v.x;
                Al[kt][r] = v.y;
            }
        if (t < Tn - 1) {
            const float xv0 = __ldg(&xg[g * Tn + t + 1]);
            const float xv1 = __ldg(&xg[(g + 8) * Tn + t + 1]);
            float lo1[4][4];
            #pragma unroll
            for (int nt = 0; nt < 4; nt++) {
                g1acc[nt][0] = fmaf(wx[nt * 2 + 0], xv0, bi0[nt * 2 + 0]);
                g1acc[nt][1] = fmaf(wx[nt * 2 + 1], xv0, bi0[nt * 2 + 1]);
                g1acc[nt][2] = fmaf(wx[nt * 2 + 0], xv1, bi0[nt * 2 + 0]);
                g1acc[nt][3] = fmaf(wx[nt * 2 + 1], xv1, bi0[nt * 2 + 1]);
                lo1[nt][0] = lo1[nt][1] = lo1[nt][2] = lo1[nt][3] = 0.f;
                #pragma unroll
                for (int kt = 0; kt < 2; kt++) {
                    mma_f16(g1acc[nt], Ah[kt], B1[nt][kt]);   // hi chain
                    mma_f16(lo1[nt],   Al[kt], B1[nt][kt]);   // lo chain (independent)
                }
            }
            #pragma unroll
            for (int nt = 0; nt < 4; nt++)
                #pragma unroll
                for (int p = 0; p < 4; p++) g1acc[nt][p] += lo1[nt][p];
        }
        {
            float lo2[4][4];
            #pragma unroll
            for (int nt = 0; nt < 4; nt++) {
                g2acc[nt][0] = bi1[nt * 2 + 0];
                g2acc[nt][1] = bi1[nt * 2 + 1];
                g2acc[nt][2] = bi1[nt * 2 + 0];
                g2acc[nt][3] = bi1[nt * 2 + 1];
                lo2[nt][0] = lo2[nt][1] = lo2[nt][2] = lo2[nt][3] = 0.f;
                #pragma unroll
                for (int kt = 0; kt < 4; kt++) {
                    mma_f16(g2acc[nt], Ah[kt], B2[nt][kt]);   // hi chain
                    mma_f16(lo2[nt],   Al[kt], B2[nt][kt]);   // lo chain
                }
            }
            #pragma unroll
            for (int nt = 0; nt < 4; nt++)
                #pragma unroll
                for (int p = 0; p < 4; p++) g2acc[nt][p] += lo2[nt][p];
        }
        // no second barrier: E(t+1) writes buf^1 while stragglers read buf
    }

    // ---- epilogue: h2(Tn-1) from g2acc, FC head ----
    {
        const int j = 8 * w + 2 * t4;
        #pragma unroll
        for (int p = 0; p < 4; p++) {
            float i_ = sigap(g2acc[0][p]);
            float f_ = sigap(g2acc[1][p]);
            float g_ = tanhap(g2acc[2][p]);
            float o_ = sigap(g2acc[3][p]);
            c2[p] = fmaf(f_, c2[p], i_ * g_);
            hf[(p < 2) ? g : (g + 8)][j + (p & 1)] = o_ * tanhap(c2[p]);
        }
    }
    __syncthreads();
    if (tid < NB) {
        float a = fc_b[0];
        #pragma unroll
        for (int k = 0; k < Hn; k++) a = fmaf(hf[tid][k], fc_w[k], a);
        out[b0 + tid] = a;
    }
}

extern "C" void kernel_launch(void* const* d_in, const int* in_sizes, int n_in,
                              void* d_out, int out_size)
{
    (void)in_sizes; (void)n_in; (void)out_size;
    const float* x      = (const float*)d_in[0];
    const float* w_ih_0 = (const float*)d_in[1];
    const float* w_hh_0 = (const float*)d_in[2];
    const float* b_ih_0 = (const float*)d_in[3];
    const float* b_hh_0 = (const float*)d_in[4];
    const float* w_ih_1 = (const float*)d_in[5];
    const float* w_hh_1 = (const float*)d_in[6];
    const float* b_ih_1 = (const float*)d_in[7];
    const float* b_hh_1 = (const float*)d_in[8];
    const float* fc_w   = (const float*)d_in[9];
    const float* fc_b   = (const float*)d_in[10];
    float* o = (float*)d_out;

    dim3 grid(Bn / NB);   // 256 blocks x 128 thr -> 2 blocks/SM, single wave
    dim3 block(NT);
    lstm_tc5<<<grid, block>>>(x, w_ih_0, w_hh_0, b_ih_0, b_hh_0,
                              w_ih_1, w_hh_1, b_ih_1, b_hh_1,
                              fc_w, fc_b, o);
}

// round 9
// speedup vs baseline: 2.7504x; 1.6990x over previous
#include <cuda_runtime.h>
#include <cuda_fp16.h>
#include <stdint.h>

// LSTM_558345748830 v8: single-pass fp16 tensor-core recurrence.
// Block = 128 threads = 4 warps = one 16-batch group; warp w owns gate ntiles
// {w, w+4, w+8, w+12} so each thread's mma accumulators hold all 4 gates and
// the elementwise phase runs entirely in registers. h exchanged via one fp16
// A-frag slab (double-buffered, compile-time buf via unroll-2). 1 barrier/step.

#define Tn 512
#define Hn 32
#define NB 16
#define NT 128
#define Bn 4096

__device__ __forceinline__ float tanhap(float x) {
    float y;
    asm("tanh.approx.f32 %0, %1;" : "=f"(y) : "f"(x));
    return y;
}
__device__ __forceinline__ float sigap(float x) {
    return fmaf(tanhap(0.5f * x), 0.5f, 0.5f);
}
__device__ __forceinline__ void mma_f16(float* d, const uint32_t* a, const uint32_t* b) {
    asm volatile(
        "mma.sync.aligned.m16n8k16.row.col.f32.f16.f16.f32 "
        "{%0,%1,%2,%3}, {%4,%5,%6,%7}, {%8,%9}, {%0,%1,%2,%3};"
        : "+f"(d[0]), "+f"(d[1]), "+f"(d[2]), "+f"(d[3])
        : "r"(a[0]), "r"(a[1]), "r"(a[2]), "r"(a[3]), "r"(b[0]), "r"(b[1]));
}
// pack {even-k -> low half, odd-k -> high half}
__device__ __forceinline__ uint32_t pack2(float e_even, float e_odd) {
    uint32_t r;
    asm("cvt.rn.f16x2.f32 %0, %1, %2;" : "=r"(r) : "f"(e_odd), "f"(e_even));
    return r;
}

__global__ __launch_bounds__(NT, 2)
void lstm_tc6(const float* __restrict__ x,
              const float* __restrict__ w_ih_0, const float* __restrict__ w_hh_0,
              const float* __restrict__ b_ih_0, const float* __restrict__ b_hh_0,
              const float* __restrict__ w_ih_1, const float* __restrict__ w_hh_1,
              const float* __restrict__ b_ih_1, const float* __restrict__ b_hh_1,
              const float* __restrict__ fc_w,   const float* __restrict__ fc_b,
              float* __restrict__ out)
{
    __shared__ uint32_t frag[2][512];    // [buf][(kt*4+r)*32+lane]; kt0-1=h1, kt2-3=h2
    __shared__ float hf[NB][Hn + 1];     // final h2 for FC head

    const int tid  = threadIdx.x;
    const int lane = tid & 31;
    const int w    = tid >> 5;        // warp 0..3
    const int g    = lane >> 2;       // mma group row 0..7
    const int t4   = lane & 3;
    const int b0   = blockIdx.x * NB;
    const float* xg = x + (size_t)b0 * Tn;

    for (int i = tid; i < 2 * 512; i += NT) (&frag[0][0])[i] = 0u;

    // ---- weight B-fragments (fp16); ntile(nt) = w + 4*nt = gate index ----
    uint32_t B1[4][2][2];    // layer1 W_hh_0 [gate][ktile][half]
    uint32_t B2[4][4][2];    // layer2 [W_ih_1 | W_hh_1]
    #pragma unroll
    for (int nt = 0; nt < 4; nt++) {
        const int n = (w + 4 * nt) * 8 + g;       // global gate row
        const float* w0 = w_hh_0 + n * Hn;
        #pragma unroll
        for (int kt = 0; kt < 2; kt++)
            #pragma unroll
            for (int h = 0; h < 2; h++) {
                int k = kt * 16 + 2 * t4 + 8 * h;
                B1[nt][kt][h] = pack2(w0[k], w0[k + 1]);
            }
        const float* wi1 = w_ih_1 + n * Hn;
        const float* wh1 = w_hh_1 + n * Hn;
        #pragma unroll
        for (int kt = 0; kt < 4; kt++) {
            const float* ws = (kt < 2) ? (wi1 + kt * 16) : (wh1 + (kt - 2) * 16);
            #pragma unroll
            for (int h = 0; h < 2; h++) {
                int k = 2 * t4 + 8 * h;
                B2[nt][kt][h] = pack2(ws[k], ws[k + 1]);
            }
        }
    }

    // ---- epilogue constants per (gate nt, parity) ----
    float wx[8], bi0[8], bi1[8];
    #pragma unroll
    for (int q = 0; q < 8; q++) {
        int n = (w + 4 * (q >> 1)) * 8 + 2 * t4 + (q & 1);
        wx[q]  = w_ih_0[n];
        bi0[q] = b_ih_0[n] + b_hh_0[n];
        bi1[q] = b_ih_1[n] + b_hh_1[n];
    }

    // frag store slot for this thread's h pair (j = 8w+2t4), row g.
    // +32 = row g+8; +256 = layer-2 region.
    const int sl1 = (((w >> 1) * 4) + (w & 1) * 2) * 32 + lane;

    float g1acc[4][4], g2acc[4][4];   // [gate][p]
    float c1[4] = {0.f, 0.f, 0.f, 0.f};
    float c2[4] = {0.f, 0.f, 0.f, 0.f};

    // ---- prologue: g1acc = gates1(0) ----
    {
        const float xv0 = __ldg(&xg[g * Tn]);
        const float xv1 = __ldg(&xg[(g + 8) * Tn]);
        #pragma unroll
        for (int nt = 0; nt < 4; nt++) {
            g1acc[nt][0] = fmaf(wx[nt * 2 + 0], xv0, bi0[nt * 2 + 0]);
            g1acc[nt][1] = fmaf(wx[nt * 2 + 1], xv0, bi0[nt * 2 + 1]);
            g1acc[nt][2] = fmaf(wx[nt * 2 + 0], xv1, bi0[nt * 2 + 0]);
            g1acc[nt][3] = fmaf(wx[nt * 2 + 1], xv1, bi0[nt * 2 + 1]);
        }
    }
    __syncthreads();

    // ---- one timestep; buf must be a literal so all frag addrs are constant ----
    auto step = [&](const int t, const int buf) {
        // ======== Phase E (registers): h1(t) from g1acc, h2(t-1) from g2acc ========
        {
            float h1v[4];
            #pragma unroll
            for (int p = 0; p < 4; p++) {
                float i_ = sigap(g1acc[0][p]);
                float f_ = sigap(g1acc[1][p]);
                float g_ = tanhap(g1acc[2][p]);
                float o_ = sigap(g1acc[3][p]);
                c1[p] = fmaf(f_, c1[p], i_ * g_);
                h1v[p] = o_ * tanhap(c1[p]);
            }
            frag[buf][sl1]      = pack2(h1v[0], h1v[1]);
            frag[buf][sl1 + 32] = pack2(h1v[2], h1v[3]);
            if (t > 0) {
                float h2v[4];
                #pragma unroll
                for (int p = 0; p < 4; p++) {
                    float i_ = sigap(g2acc[0][p]);
                    float f_ = sigap(g2acc[1][p]);
                    float g_ = tanhap(g2acc[2][p]);
                    float o_ = sigap(g2acc[3][p]);
                    c2[p] = fmaf(f_, c2[p], i_ * g_);
                    h2v[p] = o_ * tanhap(c2[p]);
                }
                frag[buf][sl1 + 256] = pack2(h2v[0], h2v[1]);
                frag[buf][sl1 + 288] = pack2(h2v[2], h2v[3]);
            }
        }
        __syncthreads();   // the ONLY barrier per step

        // ======== Phase M: g1acc <- gates1(t+1);  g2acc <- gates2(t) ========
        uint32_t Ah[4][4];
        #pragma unroll
        for (int kt = 0; kt < 4; kt++)
            #pragma unroll
            for (int r = 0; r < 4; r++)
                Ah[kt][r] = frag[buf][(kt * 4 + r) * 32 + lane];
        if (t < Tn - 1) {
            const float xv0 = __ldg(&xg[g * Tn + t + 1]);
            const float xv1 = __ldg(&xg[(g + 8) * Tn + t + 1]);
            #pragma unroll
            for (int nt = 0; nt < 4; nt++) {
                g1acc[nt][0] = fmaf(wx[nt * 2 + 0], xv0, bi0[nt * 2 + 0]);
                g1acc[nt][1] = fmaf(wx[nt * 2 + 1], xv0, bi0[nt * 2 + 1]);
                g1acc[nt][2] = fmaf(wx[nt * 2 + 0], xv1, bi0[nt * 2 + 0]);
                g1acc[nt][3] = fmaf(wx[nt * 2 + 1], xv1, bi0[nt * 2 + 1]);
                #pragma unroll
                for (int kt = 0; kt < 2; kt++)
                    mma_f16(g1acc[nt], Ah[kt], B1[nt][kt]);
            }
        }
        #pragma unroll
        for (int nt = 0; nt < 4; nt++) {
            g2acc[nt][0] = bi1[nt * 2 + 0];
            g2acc[nt][1] = bi1[nt * 2 + 1];
            g2acc[nt][2] = bi1[nt * 2 + 0];
            g2acc[nt][3] = bi1[nt * 2 + 1];
            #pragma unroll
            for (int kt = 0; kt < 4; kt++)
                mma_f16(g2acc[nt], Ah[kt], B2[nt][kt]);
        }
        // no second barrier: E(t+1) writes buf^1 while stragglers read buf
    };

    for (int t = 0; t < Tn; t += 2) {
        step(t, 0);
        step(t + 1, 1);
    }

    // ---- epilogue: h2(Tn-1) from g2acc, FC head ----
    {
        const int j = 8 * w + 2 * t4;
        #pragma unroll
        for (int p = 0; p < 4; p++) {
            float i_ = sigap(g2acc[0][p]);
            float f_ = sigap(g2acc[1][p]);
            float g_ = tanhap(g2acc[2][p]);
            float o_ = sigap(g2acc[3][p]);
            c2[p] = fmaf(f_, c2[p], i_ * g_);
            hf[(p < 2) ? g : (g + 8)][j + (p & 1)] = o_ * tanhap(c2[p]);
        }
    }
    __syncthreads();
    if (tid < NB) {
        float a = fc_b[0];
        #pragma unroll
        for (int k = 0; k < Hn; k++) a = fmaf(hf[tid][k], fc_w[k], a);
        out[b0 + tid] = a;
    }
}

extern "C" void kernel_launch(void* const* d_in, const int* in_sizes, int n_in,
                              void* d_out, int out_size)
{
    (void)in_sizes; (void)n_in; (void)out_size;
    const float* x      = (const float*)d_in[0];
    const float* w_ih_0 = (const float*)d_in[1];
    const float* w_hh_0 = (const float*)d_in[2];
    const float* b_ih_0 = (const float*)d_in[3];
    const float* b_hh_0 = (const float*)d_in[4];
    const float* w_ih_1 = (const float*)d_in[5];
    const float* w_hh_1 = (const float*)d_in[6];
    const float* b_ih_1 = (const float*)d_in[7];
    const float* b_hh_1 = (const float*)d_in[8];
    const float* fc_w   = (const float*)d_in[9];
    const float* fc_b   = (const float*)d_in[10];
    float* o = (float*)d_out;

    dim3 grid(Bn / NB);   // 256 blocks x 128 thr -> 2 blocks/SM, single wave
    dim3 block(NT);
    lstm_tc6<<<grid, block>>>(x, w_ih_0, w_hh_0, b_ih_0, b_hh_0,
                              w_ih_1, w_hh_1, b_ih_1, b_hh_1,
                              fc_w, fc_b, o);
}

// round 11
// speedup vs baseline: 2.7518x; 1.0005x over previous
#include <cuda_runtime.h>
#include <cuda_fp16.h>
#include <stdint.h>

// LSTM_558345748830 v10: v8 (single-pass fp16 mma, f32 MUFU activations,
// register-resident gates, 1 barrier/step) + corrected inter-block anti-phase
// skew: co-resident blocks are bid and bid+148, so the SECOND resident
// (bid >= 148) delays ~600 cyc once, putting its MUFU-heavy E phase over the
// partner's mma-heavy M phase for the whole run.

#define Tn 512
#define Hn 32
#define NB 16
#define NT 128
#define Bn 4096

__device__ __forceinline__ float tanhap(float x) {
    float y;
    asm("tanh.approx.f32 %0, %1;" : "=f"(y) : "f"(x));
    return y;
}
__device__ __forceinline__ float sigap(float x) {
    return fmaf(tanhap(0.5f * x), 0.5f, 0.5f);
}
__device__ __forceinline__ void mma_f16(float* d, const uint32_t* a, const uint32_t* b) {
    asm volatile(
        "mma.sync.aligned.m16n8k16.row.col.f32.f16.f16.f32 "
        "{%0,%1,%2,%3}, {%4,%5,%6,%7}, {%8,%9}, {%0,%1,%2,%3};"
        : "+f"(d[0]), "+f"(d[1]), "+f"(d[2]), "+f"(d[3])
        : "r"(a[0]), "r"(a[1]), "r"(a[2]), "r"(a[3]), "r"(b[0]), "r"(b[1]));
}
// pack {even-k -> low half, odd-k -> high half}
__device__ __forceinline__ uint32_t pack2(float e_even, float e_odd) {
    uint32_t r;
    asm("cvt.rn.f16x2.f32 %0, %1, %2;" : "=r"(r) : "f"(e_odd), "f"(e_even));
    return r;
}

__global__ __launch_bounds__(NT, 2)
void lstm_tc8(const float* __restrict__ x,
              const float* __restrict__ w_ih_0, const float* __restrict__ w_hh_0,
              const float* __restrict__ b_ih_0, const float* __restrict__ b_hh_0,
              const float* __restrict__ w_ih_1, const float* __restrict__ w_hh_1,
              const float* __restrict__ b_ih_1, const float* __restrict__ b_hh_1,
              const float* __restrict__ fc_w,   const float* __restrict__ fc_b,
              float* __restrict__ out)
{
    __shared__ uint32_t frag[2][512];    // [buf][(kt*4+r)*32+lane]; kt0-1=h1, kt2-3=h2
    __shared__ float hf[NB][Hn + 1];     // final h2 for FC head

    const int tid  = threadIdx.x;
    const int lane = tid & 31;
    const int w    = tid >> 5;        // warp 0..3
    const int g    = lane >> 2;       // mma group row 0..7
    const int t4   = lane & 3;
    const int b0   = blockIdx.x * NB;
    const float* xg = x + (size_t)b0 * Tn;

    // One-time anti-phase skew: co-resident pair on an SM = (bid, bid+148).
    // Delay the second resident ~600 cyc so its E phase overlaps partner's M.
    if (blockIdx.x >= 148) {
        long long s = clock64();
        while (clock64() - s < 600) { }
    }

    for (int i = tid; i < 2 * 512; i += NT) (&frag[0][0])[i] = 0u;

    // ---- weight B-fragments (fp16); ntile(nt) = w + 4*nt = gate index ----
    uint32_t B1[4][2][2];    // layer1 W_hh_0 [gate][ktile][half]
    uint32_t B2[4][4][2];    // layer2 [W_ih_1 | W_hh_1]
    #pragma unroll
    for (int nt = 0; nt < 4; nt++) {
        const int n = (w + 4 * nt) * 8 + g;       // global gate row
        const float* w0 = w_hh_0 + n * Hn;
        #pragma unroll
        for (int kt = 0; kt < 2; kt++)
            #pragma unroll
            for (int h = 0; h < 2; h++) {
                int k = kt * 16 + 2 * t4 + 8 * h;
                B1[nt][kt][h] = pack2(w0[k], w0[k + 1]);
            }
        const float* wi1 = w_ih_1 + n * Hn;
        const float* wh1 = w_hh_1 + n * Hn;
        #pragma unroll
        for (int kt = 0; kt < 4; kt++) {
            const float* ws = (kt < 2) ? (wi1 + kt * 16) : (wh1 + (kt - 2) * 16);
            #pragma unroll
            for (int h = 0; h < 2; h++) {
                int k = 2 * t4 + 8 * h;
                B2[nt][kt][h] = pack2(ws[k], ws[k + 1]);
            }
        }
    }

    // ---- epilogue constants per (gate nt, parity) ----
    float wx[8], bi0[8], bi1[8];
    #pragma unroll
    for (int q = 0; q < 8; q++) {
        int n = (w + 4 * (q >> 1)) * 8 + 2 * t4 + (q & 1);
        wx[q]  = w_ih_0[n];
        bi0[q] = b_ih_0[n] + b_hh_0[n];
        bi1[q] = b_ih_1[n] + b_hh_1[n];
    }

    // frag store slot for this thread's h pair (j = 8w+2t4), row g.
    // +32 = row g+8; +256 = layer-2 region.
    const int sl1 = (((w >> 1) * 4) + (w & 1) * 2) * 32 + lane;

    float g1acc[4][4], g2acc[4][4];   // [gate][p]
    float c1[4] = {0.f, 0.f, 0.f, 0.f};
    float c2[4] = {0.f, 0.f, 0.f, 0.f};

    // ---- prologue: g1acc = gates1(0) ----
    {
        const float xv0 = __ldg(&xg[g * Tn]);
        const float xv1 = __ldg(&xg[(g + 8) * Tn]);
        #pragma unroll
        for (int nt = 0; nt < 4; nt++) {
            g1acc[nt][0] = fmaf(wx[nt * 2 + 0], xv0, bi0[nt * 2 + 0]);
            g1acc[nt][1] = fmaf(wx[nt * 2 + 1], xv0, bi0[nt * 2 + 1]);
            g1acc[nt][2] = fmaf(wx[nt * 2 + 0], xv1, bi0[nt * 2 + 0]);
            g1acc[nt][3] = fmaf(wx[nt * 2 + 1], xv1, bi0[nt * 2 + 1]);
        }
    }
    __syncthreads();

    // ---- one timestep; buf is a literal so all frag addrs fold to constants ----
    auto step = [&](const int t, const int buf) {
        // ======== Phase E (registers): h1(t) from g1acc, h2(t-1) from g2acc ========
        {
            float h1v[4];
            #pragma unroll
            for (int p = 0; p < 4; p++) {
                float i_ = sigap(g1acc[0][p]);
                float f_ = sigap(g1acc[1][p]);
                float g_ = tanhap(g1acc[2][p]);
                float o_ = sigap(g1acc[3][p]);
                c1[p] = fmaf(f_, c1[p], i_ * g_);
                h1v[p] = o_ * tanhap(c1[p]);
            }
            frag[buf][sl1]      = pack2(h1v[0], h1v[1]);
            frag[buf][sl1 + 32] = pack2(h1v[2], h1v[3]);
            if (t > 0) {
                float h2v[4];
                #pragma unroll
                for (int p = 0; p < 4; p++) {
                    float i_ = sigap(g2acc[0][p]);
                    float f_ = sigap(g2acc[1][p]);
                    float g_ = tanhap(g2acc[2][p]);
                    float o_ = sigap(g2acc[3][p]);
                    c2[p] = fmaf(f_, c2[p], i_ * g_);
                    h2v[p] = o_ * tanhap(c2[p]);
                }
                frag[buf][sl1 + 256] = pack2(h2v[0], h2v[1]);
                frag[buf][sl1 + 288] = pack2(h2v[2], h2v[3]);
            }
        }
        __syncthreads();   // the ONLY barrier per step

        // ======== Phase M: g1acc <- gates1(t+1);  g2acc <- gates2(t) ========
        uint32_t Ah[4][4];
        #pragma unroll
        for (int kt = 0; kt < 4; kt++)
            #pragma unroll
            for (int r = 0; r < 4; r++)
                Ah[kt][r] = frag[buf][(kt * 4 + r) * 32 + lane];
        if (t < Tn - 1) {
            const float xv0 = __ldg(&xg[g * Tn + t + 1]);
            const float xv1 = __ldg(&xg[(g + 8) * Tn + t + 1]);
            #pragma unroll
            for (int nt = 0; nt < 4; nt++) {
                g1acc[nt][0] = fmaf(wx[nt * 2 + 0], xv0, bi0[nt * 2 + 0]);
                g1acc[nt][1] = fmaf(wx[nt * 2 + 1], xv0, bi0[nt * 2 + 1]);
                g1acc[nt][2] = fmaf(wx[nt * 2 + 0], xv1, bi0[nt * 2 + 0]);
                g1acc[nt][3] = fmaf(wx[nt * 2 + 1], xv1, bi0[nt * 2 + 1]);
                #pragma unroll
                for (int kt = 0; kt < 2; kt++)
                    mma_f16(g1acc[nt], Ah[kt], B1[nt][kt]);
            }
        }
        #pragma unroll
        for (int nt = 0; nt < 4; nt++) {
            g2acc[nt][0] = bi1[nt * 2 + 0];
            g2acc[nt][1] = bi1[nt * 2 + 1];
            g2acc[nt][2] = bi1[nt * 2 + 0];
            g2acc[nt][3] = bi1[nt * 2 + 1];
            #pragma unroll
            for (int kt = 0; kt < 4; kt++)
                mma_f16(g2acc[nt], Ah[kt], B2[nt][kt]);
        }
        // no second barrier: E(t+1) writes buf^1 while stragglers read buf
    };

    for (int t = 0; t < Tn; t += 2) {
        step(t, 0);
        step(t + 1, 1);
    }

    // ---- epilogue: h2(Tn-1) from g2acc, FC head ----
    {
        const int j = 8 * w + 2 * t4;
        #pragma unroll
        for (int p = 0; p < 4; p++) {
            float i_ = sigap(g2acc[0][p]);
            float f_ = sigap(g2acc[1][p]);
            float g_ = tanhap(g2acc[2][p]);
            float o_ = sigap(g2acc[3][p]);
            c2[p] = fmaf(f_, c2[p], i_ * g_);
            hf[(p < 2) ? g : (g + 8)][j + (p & 1)] = o_ * tanhap(c2[p]);
        }
    }
    __syncthreads();
    if (tid < NB) {
        float a = fc_b[0];
        #pragma unroll
        for (int k = 0; k < Hn; k++) a = fmaf(hf[tid][k], fc_w[k], a);
        out[b0 + tid] = a;
    }
}

extern "C" void kernel_launch(void* const* d_in, const int* in_sizes, int n_in,
                              void* d_out, int out_size)
{
    (void)in_sizes; (void)n_in; (void)out_size;
    const float* x      = (const float*)d_in[0];
    const float* w_ih_0 = (const float*)d_in[1];
    const float* w_hh_0 = (const float*)d_in[2];
    const float* b_ih_0 = (const float*)d_in[3];
    const float* b_hh_0 = (const float*)d_in[4];
    const float* w_ih_1 = (const float*)d_in[5];
    const float* w_hh_1 = (const float*)d_in[6];
    const float* b_ih_1 = (const float*)d_in[7];
    const float* b_hh_1 = (const float*)d_in[8];
    const float* fc_w   = (const float*)d_in[9];
    const float* fc_b   = (const float*)d_in[10];
    float* o = (float*)d_out;

    dim3 grid(Bn / NB);   // 256 blocks x 128 thr -> 2 blocks/SM, single wave
    dim3 block(NT);
    lstm_tc8<<<grid, block>>>(x, w_ih_0, w_hh_0, b_ih_0, b_hh_0,
                              w_ih_1, w_hh_1, b_ih_1, b_hh_1,
                              fc_w, fc_b, o);
}

// round 12
// speedup vs baseline: 2.7733x; 1.0078x over previous
#include <cuda_runtime.h>
#include <cuda_fp16.h>
#include <stdint.h>

// LSTM_558345748830 v11: fused-phase fp16 tensor-core recurrence.
// Block = 128 threads = 4 warps = one 16-batch group; warp w owns gate ntiles
// {w, w+4, w+8, w+12} so each thread's mma accumulators hold all 4 gates.
// ONE fused phase per step: LDS A -> g1 mma(t+1) -> g2 mma(t) -> h1(t+1)
// activations (overlap g2 mma) -> h2(t) activations -> store frags -> barrier.
// MUFU and tensor work live in the same scheduling region => pipes overlap.

#define Tn 512
#define Hn 32
#define NB 16
#define NT 128
#define Bn 4096

__device__ __forceinline__ float tanhap(float x) {
    float y;
    asm("tanh.approx.f32 %0, %1;" : "=f"(y) : "f"(x));
    return y;
}
__device__ __forceinline__ float sigap(float x) {
    return fmaf(tanhap(0.5f * x), 0.5f, 0.5f);
}
__device__ __forceinline__ void mma_f16(float* d, const uint32_t* a, const uint32_t* b) {
    asm volatile(
        "mma.sync.aligned.m16n8k16.row.col.f32.f16.f16.f32 "
        "{%0,%1,%2,%3}, {%4,%5,%6,%7}, {%8,%9}, {%0,%1,%2,%3};"
        : "+f"(d[0]), "+f"(d[1]), "+f"(d[2]), "+f"(d[3])
        : "r"(a[0]), "r"(a[1]), "r"(a[2]), "r"(a[3]), "r"(b[0]), "r"(b[1]));
}
// pack {even-k -> low half, odd-k -> high half}
__device__ __forceinline__ uint32_t pack2(float e_even, float e_odd) {
    uint32_t r;
    asm("cvt.rn.f16x2.f32 %0, %1, %2;" : "=r"(r) : "f"(e_odd), "f"(e_even));
    return r;
}

__global__ __launch_bounds__(NT, 2)
void lstm_tc9(const float* __restrict__ x,
              const float* __restrict__ w_ih_0, const float* __restrict__ w_hh_0,
              const float* __restrict__ b_ih_0, const float* __restrict__ b_hh_0,
              const float* __restrict__ w_ih_1, const float* __restrict__ w_hh_1,
              const float* __restrict__ b_ih_1, const float* __restrict__ b_hh_1,
              const float* __restrict__ fc_w,   const float* __restrict__ fc_b,
              float* __restrict__ out)
{
    __shared__ uint32_t frag[2][512];    // [buf][(kt*4+r)*32+lane]; kt0-1=h1, kt2-3=h2
    __shared__ float hf[NB][Hn + 1];     // final h2 for FC head

    const int tid  = threadIdx.x;
    const int lane = tid & 31;
    const int w    = tid >> 5;        // warp 0..3
    const int g    = lane >> 2;       // mma group row 0..7
    const int t4   = lane & 3;
    const int b0   = blockIdx.x * NB;
    const float* xg = x + (size_t)b0 * Tn;

    for (int i = tid; i < 2 * 512; i += NT) (&frag[0][0])[i] = 0u;

    // ---- weight B-fragments (fp16); ntile(nt) = w + 4*nt = gate index ----
    uint32_t B1[4][2][2];    // layer1 W_hh_0 [gate][ktile][half]
    uint32_t B2[4][4][2];    // layer2 [W_ih_1 | W_hh_1]
    #pragma unroll
    for (int nt = 0; nt < 4; nt++) {
        const int n = (w + 4 * nt) * 8 + g;       // global gate row
        const float* w0 = w_hh_0 + n * Hn;
        #pragma unroll
        for (int kt = 0; kt < 2; kt++)
            #pragma unroll
            for (int h = 0; h < 2; h++) {
                int k = kt * 16 + 2 * t4 + 8 * h;
                B1[nt][kt][h] = pack2(w0[k], w0[k + 1]);
            }
        const float* wi1 = w_ih_1 + n * Hn;
        const float* wh1 = w_hh_1 + n * Hn;
        #pragma unroll
        for (int kt = 0; kt < 4; kt++) {
            const float* ws = (kt < 2) ? (wi1 + kt * 16) : (wh1 + (kt - 2) * 16);
            #pragma unroll
            for (int h = 0; h < 2; h++) {
                int k = 2 * t4 + 8 * h;
                B2[nt][kt][h] = pack2(ws[k], ws[k + 1]);
            }
        }
    }

    // ---- epilogue constants per (gate nt, parity) ----
    float wx[8], bi0[8], bi1[8];
    #pragma unroll
    for (int q = 0; q < 8; q++) {
        int n = (w + 4 * (q >> 1)) * 8 + 2 * t4 + (q & 1);
        wx[q]  = w_ih_0[n];
        bi0[q] = b_ih_0[n] + b_hh_0[n];
        bi1[q] = b_ih_1[n] + b_hh_1[n];
    }

    // frag store slot for this thread's h pair (j = 8w+2t4), row g.
    // +32 = row g+8; +256 = layer-2 region.
    const int sl1 = (((w >> 1) * 4) + (w & 1) * 2) * 32 + lane;
    const int j   = 8 * w + 2 * t4;

    float g1acc[4][4], g2acc[4][4];   // [gate][p]
    float c1[4] = {0.f, 0.f, 0.f, 0.f};
    float c2[4] = {0.f, 0.f, 0.f, 0.f};

    // ---- prologue: gates1(0) -> h1(0) -> frag[0] ----
    {
        const float xv0 = __ldg(&xg[g * Tn]);
        const float xv1 = __ldg(&xg[(g + 8) * Tn]);
        #pragma unroll
        for (int nt = 0; nt < 4; nt++) {
            g1acc[nt][0] = fmaf(wx[nt * 2 + 0], xv0, bi0[nt * 2 + 0]);
            g1acc[nt][1] = fmaf(wx[nt * 2 + 1], xv0, bi0[nt * 2 + 1]);
            g1acc[nt][2] = fmaf(wx[nt * 2 + 0], xv1, bi0[nt * 2 + 0]);
            g1acc[nt][3] = fmaf(wx[nt * 2 + 1], xv1, bi0[nt * 2 + 1]);
        }
        float h1v[4];
        #pragma unroll
        for (int p = 0; p < 4; p++) {
            float i_ = sigap(g1acc[0][p]);
            float f_ = sigap(g1acc[1][p]);
            float g_ = tanhap(g1acc[2][p]);
            float o_ = sigap(g1acc[3][p]);
            c1[p] = fmaf(f_, c1[p], i_ * g_);
            h1v[p] = o_ * tanhap(c1[p]);
        }
        frag[0][sl1]      = pack2(h1v[0], h1v[1]);
        frag[0][sl1 + 32] = pack2(h1v[2], h1v[3]);
        // h2(-1) region already zero
    }
    __syncthreads();

    // ---- one fused phase; buf literal so frag addrs fold to constants ----
    // frag[buf] holds h1(t), h2(t-1). Phase computes gates1(t+1), gates2(t),
    // then h1(t+1), h2(t) -> frag[buf^1]. Barrier at END of phase.
    auto phase = [&](const int t, const int buf) {
        const bool last = (t == Tn - 1);
        uint32_t Ah[4][4];
        #pragma unroll
        for (int kt = 0; kt < 4; kt++)
            #pragma unroll
            for (int r = 0; r < 4; r++)
                Ah[kt][r] = frag[buf][(kt * 4 + r) * 32 + lane];

        if (!last) {   // gates1(t+1)
            const float xv0 = __ldg(&xg[g * Tn + t + 1]);
            const float xv1 = __ldg(&xg[(g + 8) * Tn + t + 1]);
            #pragma unroll
            for (int nt = 0; nt < 4; nt++) {
                g1acc[nt][0] = fmaf(wx[nt * 2 + 0], xv0, bi0[nt * 2 + 0]);
                g1acc[nt][1] = fmaf(wx[nt * 2 + 1], xv0, bi0[nt * 2 + 1]);
                g1acc[nt][2] = fmaf(wx[nt * 2 + 0], xv1, bi0[nt * 2 + 0]);
                g1acc[nt][3] = fmaf(wx[nt * 2 + 1], xv1, bi0[nt * 2 + 1]);
                #pragma unroll
                for (int kt = 0; kt < 2; kt++)
                    mma_f16(g1acc[nt], Ah[kt], B1[nt][kt]);
            }
        }
        // gates2(t) — independent of g1acc; overlaps h1 activations below
        #pragma unroll
        for (int nt = 0; nt < 4; nt++) {
            g2acc[nt][0] = bi1[nt * 2 + 0];
            g2acc[nt][1] = bi1[nt * 2 + 1];
            g2acc[nt][2] = bi1[nt * 2 + 0];
            g2acc[nt][3] = bi1[nt * 2 + 1];
            #pragma unroll
            for (int kt = 0; kt < 4; kt++)
                mma_f16(g2acc[nt], Ah[kt], B2[nt][kt]);
        }
        if (!last) {   // h1(t+1): depends only on g1acc -> overlaps g2 mma
            float h1v[4];
            #pragma unroll
            for (int p = 0; p < 4; p++) {
                float i_ = sigap(g1acc[0][p]);
                float f_ = sigap(g1acc[1][p]);
                float g_ = tanhap(g1acc[2][p]);
                float o_ = sigap(g1acc[3][p]);
                c1[p] = fmaf(f_, c1[p], i_ * g_);
                h1v[p] = o_ * tanhap(c1[p]);
            }
            frag[buf ^ 1][sl1]      = pack2(h1v[0], h1v[1]);
            frag[buf ^ 1][sl1 + 32] = pack2(h1v[2], h1v[3]);
        }
        {   // h2(t)
            float h2v[4];
            #pragma unroll
            for (int p = 0; p < 4; p++) {
                float i_ = sigap(g2acc[0][p]);
                float f_ = sigap(g2acc[1][p]);
                float g_ = tanhap(g2acc[2][p]);
                float o_ = sigap(g2acc[3][p]);
                c2[p] = fmaf(f_, c2[p], i_ * g_);
                h2v[p] = o_ * tanhap(c2[p]);
            }
            if (!last) {
                frag[buf ^ 1][sl1 + 256] = pack2(h2v[0], h2v[1]);
                frag[buf ^ 1][sl1 + 288] = pack2(h2v[2], h2v[3]);
            } else {
                #pragma unroll
                for (int p = 0; p < 4; p++)
                    hf[(p < 2) ? g : (g + 8)][j + (p & 1)] = h2v[p];
            }
        }
        __syncthreads();
    };

    for (int t = 0; t < Tn; t += 2) {
        phase(t, 0);
        phase(t + 1, 1);
    }

    // ---- FC head ----
    if (tid < NB) {
        float a = fc_b[0];
        #pragma unroll
        for (int k = 0; k < Hn; k++) a = fmaf(hf[tid][k], fc_w[k], a);
        out[b0 + tid] = a;
    }
}

extern "C" void kernel_launch(void* const* d_in, const int* in_sizes, int n_in,
                              void* d_out, int out_size)
{
    (void)in_sizes; (void)n_in; (void)out_size;
    const float* x      = (const float*)d_in[0];
    const float* w_ih_0 = (const float*)d_in[1];
    const float* w_hh_0 = (const float*)d_in[2];
    const float* b_ih_0 = (const float*)d_in[3];
    const float* b_hh_0 = (const float*)d_in[4];
    const float* w_ih_1 = (const float*)d_in[5];
    const float* w_hh_1 = (const float*)d_in[6];
    const float* b_ih_1 = (const float*)d_in[7];
    const float* b_hh_1 = (const float*)d_in[8];
    const float* fc_w   = (const float*)d_in[9];
    const float* fc_b   = (const float*)d_in[10];
    float* o = (float*)d_out;

    dim3 grid(Bn / NB);   // 256 blocks x 128 thr -> 2 blocks/SM, single wave
    dim3 block(NT);
    lstm_tc9<<<grid, block>>>(x, w_ih_0, w_hh_0, b_ih_0, b_hh_0,
                              w_ih_1, w_hh_1, b_ih_1, b_hh_1,
                              fc_w, fc_b, o);
}